// round 1
// baseline (speedup 1.0000x reference)
#include <cuda_runtime.h>
#include <cuda_bf16.h>

#define BATCH 8
#define CHANS 4
#define H 512
#define W 512
#define NPIX (BATCH * H * W)          // 2,097,152
#define NROWS (BATCH * H)             // 4096
#define LOSS_BLOCKS (NPIX / 256)      // 8192

// Scratch: per-pixel horizontal distances (x = dist-to-fg, y = dist-to-bg), capped.
__device__ uchar2 g_rcol[NPIX];
__device__ double g_bsum[LOSS_BLOCKS];

// Nearest-set-bit distance along a row, for bit j of word `cur`, with
// neighbor words prv/nxt (0 if outside the row). Any value > 30 is "far";
// max possible returned distance here is 63, sentinel 127 when nothing found.
__device__ __forceinline__ int rowdist1(unsigned cur, unsigned prv, unsigned nxt, int j) {
    unsigned r = cur >> j;
    int rd = r ? (__ffs((int)r) - 1)
               : (nxt ? (32 - j) + (__ffs((int)nxt) - 1) : 127);
    unsigned l = cur << (31 - j);
    int ld = l ? __clz((int)l)
               : (prv ? (j + 1) + __clz((int)prv) : 127);
    return min(rd, ld);
}

// Kernel 1: one block per image row. Build fg bitmask via ballot, then compute
// horizontal capped distances for both fg and bg sets.
__global__ void rowdist_kernel(const int* __restrict__ yt) {
    __shared__ unsigned smask[16];
    const int row = blockIdx.x;        // 0 .. NROWS-1  (= b*H + y)
    const int x = threadIdx.x;         // 0 .. 511
    const int fg = yt[row * W + x] > 0;
    unsigned bal = __ballot_sync(0xFFFFFFFFu, fg);
    if ((x & 31) == 0) smask[x >> 5] = bal;
    __syncthreads();

    const int i = x >> 5, j = x & 31;
    unsigned cur = smask[i];
    unsigned prv = (i > 0)  ? smask[i - 1] : 0u;
    unsigned nxt = (i < 15) ? smask[i + 1] : 0u;

    int rfg = rowdist1(cur, prv, nxt, j);
    // bg = complement (all 512 bits of the row are valid; out-of-row words are 0)
    unsigned curc = ~cur;
    unsigned prvc = (i > 0)  ? ~smask[i - 1] : 0u;
    unsigned nxtc = (i < 15) ? ~smask[i + 1] : 0u;
    int rbg = rowdist1(curc, prvc, nxtc, j);

    uchar2 out;
    out.x = (unsigned char)min(rfg, 127);
    out.y = (unsigned char)min(rbg, 127);
    g_rcol[row * W + x] = out;
}

// Kernel 2: vertical distance combine (early-exit window), softmax, weighted
// squared error, per-block reduction.
__global__ void loss_kernel(const float* __restrict__ logits) {
    const int x = blockIdx.x * blockDim.x + threadIdx.x;  // 0..511 (gridDim.x=2, 256 thr)
    const int y = blockIdx.y;
    const int b = blockIdx.z;
    const int pix = (b * H + y) * W + x;

    uchar2 rc = g_rcol[pix];
    int bfg = rc.x;
    int bbg = rc.y;
    const uchar2* col = g_rcol + (size_t)(b * H) * W + x;

    #pragma unroll 1
    for (int d = 1; d <= 30; ++d) {
        if (bfg <= d && bbg <= d) break;     // candidates at step d are >= d
        int ru = 127, bu = 127, rv = 127, bv = 127;
        if (y - d >= 0) { uchar2 u = col[(size_t)(y - d) * W]; ru = u.x; bu = u.y; }
        if (y + d <  H) { uchar2 v = col[(size_t)(y + d) * W]; rv = v.x; bv = v.y; }
        bfg = min(bfg, max(d, min(ru, rv)));
        bbg = min(bbg, max(d, min(bu, bv)));
    }

    float dfg = (bfg <= 30) ? (float)bfg : 200.0f;
    float dbg = (bbg <= 30) ? (float)bbg : 200.0f;
    float wmap = dfg * dfg + dbg * dbg;

    // softmax over 4 channels; global_probs = max over channels 1..3
    const float* lp = logits + (size_t)b * CHANS * H * W + (size_t)y * W + x;
    float l0 = lp[0];
    float l1 = lp[(size_t)H * W];
    float l2 = lp[2 * (size_t)H * W];
    float l3 = lp[3 * (size_t)H * W];
    float m  = fmaxf(fmaxf(l0, l1), fmaxf(l2, l3));
    float e0 = __expf(l0 - m), e1 = __expf(l1 - m);
    float e2 = __expf(l2 - m), e3 = __expf(l3 - m);
    float inv = 1.0f / (e0 + e1 + e2 + e3);
    float gp  = fmaxf(fmaxf(e1, e2), e3) * inv;

    float gt = (rc.x == 0) ? 1.0f : 0.0f;    // fg pixel <=> horizontal fg dist == 0
    float diff = gp - gt;
    float v = diff * diff * wmap;

    // deterministic block reduction (warp shuffle + shared)
    #pragma unroll
    for (int o = 16; o > 0; o >>= 1) v += __shfl_down_sync(0xFFFFFFFFu, v, o);
    __shared__ float wsum[8];
    int lane = threadIdx.x & 31, wid = threadIdx.x >> 5;
    if (lane == 0) wsum[wid] = v;
    __syncthreads();
    if (threadIdx.x == 0) {
        double s = 0.0;
        #pragma unroll
        for (int i = 0; i < 8; ++i) s += (double)wsum[i];
        int bid = (blockIdx.z * gridDim.y + blockIdx.y) * gridDim.x + blockIdx.x;
        g_bsum[bid] = s;
    }
}

// Kernel 3: deterministic final reduction + mean.
__global__ void final_kernel(float* __restrict__ out) {
    __shared__ double sh[256];
    double s = 0.0;
    for (int i = threadIdx.x; i < LOSS_BLOCKS; i += 256) s += g_bsum[i];
    sh[threadIdx.x] = s;
    __syncthreads();
    #pragma unroll
    for (int o = 128; o > 0; o >>= 1) {
        if (threadIdx.x < o) sh[threadIdx.x] += sh[threadIdx.x + o];
        __syncthreads();
    }
    if (threadIdx.x == 0) out[0] = (float)(sh[0] / (double)NPIX);
}

extern "C" void kernel_launch(void* const* d_in, const int* in_sizes, int n_in,
                              void* d_out, int out_size) {
    const float* logits = (const float*)d_in[0];
    const int*   y_true = (const int*)d_in[1];
    float*       out    = (float*)d_out;

    rowdist_kernel<<<NROWS, W>>>(y_true);

    dim3 blk(256, 1, 1);
    dim3 grd(W / 256, H, BATCH);
    loss_kernel<<<grd, blk>>>(logits);

    final_kernel<<<1, 256>>>(out);
}

// round 2
// speedup vs baseline: 1.1730x; 1.1730x over previous
#include <cuda_runtime.h>
#include <cuda_bf16.h>

#define BATCH 8
#define CHANS 4
#define H 512
#define W 512
#define NPIX (BATCH * H * W)          // 2,097,152
#define NROWS (BATCH * H)             // 4096
#define LOSS_BLOCKS (NROWS)           // one block per (b,y) row: 4096

// Scratch: per-pixel horizontal distances (byte pairs: fg, bg), capped at 127.
__device__ uchar2 g_rcol[NPIX];
__device__ double g_bsum[LOSS_BLOCKS];

// Nearest-set-bit distance along a row, for bit j of word `cur`, with neighbor
// words prv/nxt (0 outside row). Exact for all distances <= 31 (all that matter);
// 127 = "far".
__device__ __forceinline__ int rowdist1(unsigned cur, unsigned prv, unsigned nxt, int j) {
    unsigned r = cur >> j;
    int rd = r ? (__ffs((int)r) - 1)
               : (nxt ? (32 - j) + (__ffs((int)nxt) - 1) : 127);
    unsigned l = cur << (31 - j);
    int ld = l ? __clz((int)l)
               : (prv ? (j + 1) + __clz((int)prv) : 127);
    return min(min(rd, ld), 127);
}

// Compress nibble-bytes of a u32 (4 bytes, low nibble each) into 16 bits.
__device__ __forceinline__ unsigned nib_compress(unsigned a) {
    return (a & 0xFu) | ((a >> 4) & 0xF0u) | ((a >> 8) & 0xF00u) | ((a >> 12) & 0xF000u);
}

// Kernel 1: 4 rows per block, 128 threads per row, 4 pixels per thread.
__global__ void rowdist_kernel(const int4* __restrict__ yt4) {
    __shared__ unsigned char nib[4][128];
    __shared__ unsigned words[4][16];
    const int r = threadIdx.x >> 7;       // row within block (0..3)
    const int t = threadIdx.x & 127;      // 0..127, covers pixels 4t..4t+3
    const int row = blockIdx.x * 4 + r;   // 0..NROWS-1

    int4 v = yt4[(size_t)row * (W / 4) + t];
    unsigned n = (unsigned)(v.x > 0) | ((unsigned)(v.y > 0) << 1)
               | ((unsigned)(v.z > 0) << 2) | ((unsigned)(v.w > 0) << 3);
    nib[r][t] = (unsigned char)n;
    __syncthreads();

    if (threadIdx.x < 64) {               // 4 rows x 16 words
        int rr = threadIdx.x >> 4, i = threadIdx.x & 15;
        const unsigned* p = (const unsigned*)nib[rr];
        unsigned a = p[2 * i], b = p[2 * i + 1];
        words[rr][i] = nib_compress(a) | (nib_compress(b) << 16);
    }
    __syncthreads();

    const int i = t >> 3;                 // word index 0..15
    const int jb = (t & 7) * 4;           // base bit within word
    unsigned cur = words[r][i];
    unsigned prv = (i > 0)  ? words[r][i - 1]  : 0u;
    unsigned nxt = (i < 15) ? words[r][i + 1]  : 0u;
    unsigned curc = ~cur;
    unsigned prvc = (i > 0)  ? ~words[r][i - 1] : 0u;
    unsigned nxtc = (i < 15) ? ~words[r][i + 1] : 0u;

    unsigned long long out = 0ull;
    #pragma unroll
    for (int k = 0; k < 4; ++k) {
        unsigned long long rfg = (unsigned)rowdist1(cur,  prv,  nxt,  jb + k);
        unsigned long long rbg = (unsigned)rowdist1(curc, prvc, nxtc, jb + k);
        out |= (rfg | (rbg << 8)) << (16 * k);
    }
    ((unsigned long long*)g_rcol)[(size_t)row * 128 + t] = out;
}

// Kernel 2: vertical combine (early-exit, 8-byte taps), softmax, weighted
// squared error, per-block reduction. One block per (b,y) row; 4 px/thread.
__global__ void loss_kernel(const float4* __restrict__ logits4) {
    const int t = threadIdx.x;            // 0..127
    const int y = blockIdx.y;
    const int b = blockIdx.z;

    union U8 { unsigned long long u; unsigned char c[8]; };
    const unsigned long long* col =
        (const unsigned long long*)g_rcol + (size_t)b * H * 128 + t;

    U8 self; self.u = col[(size_t)y * 128];
    int bfg[4], bbg[4];
    #pragma unroll
    for (int k = 0; k < 4; ++k) { bfg[k] = self.c[2 * k]; bbg[k] = self.c[2 * k + 1]; }

    #pragma unroll 1
    for (int d = 1; d <= 30; ++d) {
        int mx = max(max(max(bfg[0], bfg[1]), max(bfg[2], bfg[3])),
                     max(max(bbg[0], bbg[1]), max(bbg[2], bbg[3])));
        if (mx <= d) break;               // candidates at step d are >= d
        U8 up, dn;
        up.u = (y - d >= 0) ? col[(size_t)(y - d) * 128] : 0x7f7f7f7f7f7f7f7full;
        dn.u = (y + d <  H) ? col[(size_t)(y + d) * 128] : 0x7f7f7f7f7f7f7f7full;
        #pragma unroll
        for (int k = 0; k < 4; ++k) {
            bfg[k] = min(bfg[k], max(d, min((int)up.c[2 * k],     (int)dn.c[2 * k])));
            bbg[k] = min(bbg[k], max(d, min((int)up.c[2 * k + 1], (int)dn.c[2 * k + 1])));
        }
    }

    // logits: float4 covers the same 4 pixels; channel stride = H*W floats = H*128 float4
    const float4* lp = logits4 + ((size_t)b * CHANS * H + y) * 128 + t;
    float4 L0 = lp[0];
    float4 L1 = lp[(size_t)H * 128];
    float4 L2 = lp[2 * (size_t)H * 128];
    float4 L3 = lp[3 * (size_t)H * 128];
    float l0[4] = {L0.x, L0.y, L0.z, L0.w};
    float l1[4] = {L1.x, L1.y, L1.z, L1.w};
    float l2[4] = {L2.x, L2.y, L2.z, L2.w};
    float l3[4] = {L3.x, L3.y, L3.z, L3.w};

    float v = 0.0f;
    #pragma unroll
    for (int k = 0; k < 4; ++k) {
        float dfg = (bfg[k] <= 30) ? (float)bfg[k] : 200.0f;
        float dbg = (bbg[k] <= 30) ? (float)bbg[k] : 200.0f;
        float wmap = dfg * dfg + dbg * dbg;

        float m  = fmaxf(fmaxf(l0[k], l1[k]), fmaxf(l2[k], l3[k]));
        float e0 = __expf(l0[k] - m), e1 = __expf(l1[k] - m);
        float e2 = __expf(l2[k] - m), e3 = __expf(l3[k] - m);
        float inv = 1.0f / (e0 + e1 + e2 + e3);
        float gp  = fmaxf(fmaxf(e1, e2), e3) * inv;

        float gt = (self.c[2 * k] == 0) ? 1.0f : 0.0f;
        float diff = gp - gt;
        v += diff * diff * wmap;
    }

    // deterministic block reduction (4 warps)
    #pragma unroll
    for (int o = 16; o > 0; o >>= 1) v += __shfl_down_sync(0xFFFFFFFFu, v, o);
    __shared__ float wsum[4];
    int lane = threadIdx.x & 31, wid = threadIdx.x >> 5;
    if (lane == 0) wsum[wid] = v;
    __syncthreads();
    if (threadIdx.x == 0) {
        double s = (double)wsum[0] + (double)wsum[1] + (double)wsum[2] + (double)wsum[3];
        g_bsum[blockIdx.z * H + blockIdx.y] = s;
    }
}

// Kernel 3: deterministic final reduction + mean.
__global__ void final_kernel(float* __restrict__ out) {
    __shared__ double sh[256];
    double s = 0.0;
    for (int i = threadIdx.x; i < LOSS_BLOCKS; i += 256) s += g_bsum[i];
    sh[threadIdx.x] = s;
    __syncthreads();
    #pragma unroll
    for (int o = 128; o > 0; o >>= 1) {
        if (threadIdx.x < o) sh[threadIdx.x] += sh[threadIdx.x + o];
        __syncthreads();
    }
    if (threadIdx.x == 0) out[0] = (float)(sh[0] / (double)NPIX);
}

extern "C" void kernel_launch(void* const* d_in, const int* in_sizes, int n_in,
                              void* d_out, int out_size) {
    const float* logits = (const float*)d_in[0];
    const int*   y_true = (const int*)d_in[1];
    float*       out    = (float*)d_out;

    rowdist_kernel<<<NROWS / 4, 512>>>((const int4*)y_true);

    dim3 blk(128, 1, 1);
    dim3 grd(1, H, BATCH);
    loss_kernel<<<grd, blk>>>((const float4*)logits);

    final_kernel<<<1, 256>>>(out);
}